// round 6
// baseline (speedup 1.0000x reference)
#include <cuda_runtime.h>
#include <stdint.h>

#define NCOLS   24576
#define THREADS 1024
#define NWARPS  (THREADS / 32)            // 32
#define EPT4    (NCOLS / (THREADS * 4))   // 6 uint4 per thread (24 floats, register-resident)
#define HWORDS  2048                      // 11-bit histogram region
#define CAP     1184                      // candidate capacity (inside h region)
// smem words: hist + warp-totals(32) + select-out(4) + vars(8)
#define SMEM_WORDS (HWORDS + NWARPS + 4 + 8)
#define SMEM_BYTES (SMEM_WORDS * 4)

// ---- order-preserving float<->key transform (bigger key = bigger float)
__device__ __forceinline__ uint32_t f2key(float f) {
    uint32_t b = __float_as_uint(f);
    return (b & 0x80000000u) ? ~b : (b | 0x80000000u);
}
__device__ __forceinline__ float key2f(uint32_t k) {
    uint32_t b = (k & 0x80000000u) ? (k ^ 0x80000000u) : ~k;
    return __uint_as_float(b);
}

// Block-wide suffix select over histogram h: thread t owns bins [t*G, t*G+G).
// Finds bin b = max{b : count(bins >= b) >= rank}; writes s_sel[0]=bin,
// s_sel[1]=rank-within-bin (1-based), s_sel[2]=bin count.
__device__ __forceinline__ void suffix_select(
    const uint32_t* h, int G, int nbins, int rank,
    uint32_t* s_wtot, uint32_t* s_sel)
{
    const int t = threadIdx.x, lane = t & 31, warp = t >> 5;
    int v = 0;
    if (t * G < nbins) {
        #pragma unroll
        for (int j = 0; j < 4; j++)
            if (j < G) v += (int)h[t * G + j];
    }
    int s = v;
    #pragma unroll
    for (int d = 1; d < 32; d <<= 1) {
        int o = __shfl_down_sync(0xffffffffu, s, d);
        if (lane + d < 32) s += o;
    }
    if (lane == 0) s_wtot[warp] = (uint32_t)s;
    __syncthreads();
    if (warp == 0) {
        int wv = (lane < NWARPS) ? (int)s_wtot[lane] : 0;
        int ws = wv;
        #pragma unroll
        for (int d = 1; d < 32; d <<= 1) {
            int o = __shfl_down_sync(0xffffffffu, ws, d);
            if (lane + d < 32) ws += o;
        }
        if (lane < NWARPS) s_wtot[lane] = (uint32_t)(ws - wv);  // strictly-above-warp sum
    }
    __syncthreads();
    int S = s + (int)s_wtot[warp];
    int above = S - v;
    if (t * G < nbins && S >= rank && above < rank) {
        int cum = above;
        for (int j = G - 1; j >= 0; j--) {
            int c = (int)h[t * G + j];
            if (cum + c >= rank) {
                s_sel[0] = (uint32_t)(t * G + j);
                s_sel[1] = (uint32_t)(rank - cum);
                s_sel[2] = (uint32_t)c;
                break;
            }
            cum += c;
        }
    }
    __syncthreads();
}

__device__ __forceinline__ void clear_hist(uint32_t* h) {
    #pragma unroll
    for (int i = 0; i < HWORDS / THREADS; i++) h[i * THREADS + threadIdx.x] = 0;
}

__global__ void __launch_bounds__(THREADS, 1)
topk_filter_kernel(const float* __restrict__ x, const int* __restrict__ kptr,
                   float* __restrict__ out)
{
    extern __shared__ uint32_t sm[];
    uint32_t* h      = sm;                      // HWORDS
    uint32_t* s_wtot = h + HWORDS;              // NWARPS
    uint32_t* s_sel  = s_wtot + NWARPS;         // 4
    uint32_t* s_var  = s_sel + 4;               // 8: [0]=cand ctr, [1]=cut lo, [2]=cut hi, [3]=bsearch ctr
    // candidate arrays live inside h (used only after maxes-select consumed h)
    uint32_t* ckey = h + 256;
    uint16_t* cidx = (uint16_t*)(ckey + CAP);   // 256 + 1184 + 592 = 2032 <= 2048 words

    const int t    = threadIdx.x;
    const int lane = t & 31;
    const int k    = *kptr;

    const float4* xin  = (const float4*)(x   + (size_t)blockIdx.x * NCOLS);
    float4*       xout = (float4*)      (out + (size_t)blockIdx.x * NCOLS);

    if (k >= NCOLS) {
        #pragma unroll
        for (int i = 0; i < EPT4; i++) xout[i * THREADS + t] = __ldcs(&xin[i * THREADS + t]);
        return;
    }
    if (k <= 0) {
        float4 z = make_float4(0.f, 0.f, 0.f, 0.f);
        #pragma unroll
        for (int i = 0; i < EPT4; i++) xout[i * THREADS + t] = z;
        return;
    }

    bool fb = (k > THREADS);   // sampled-threshold guarantee needs k <= 1024

    // ---------------- P0: load to REGISTERS + key transform + per-thread max ----------------
    if (t == 0) s_var[0] = 0;
    clear_hist(h);

    uint4 kk[EPT4];
    uint32_t mymax = 0;
    #pragma unroll
    for (int i = 0; i < EPT4; i++) {
        float4 v = __ldcs(&xin[i * THREADS + t]);
        kk[i].x = f2key(v.x); kk[i].y = f2key(v.y);
        kk[i].z = f2key(v.z); kk[i].w = f2key(v.w);
        uint32_t m0 = max(kk[i].x, kk[i].y), m1 = max(kk[i].z, kk[i].w);
        mymax = max(mymax, max(m0, m1));
    }
    __syncthreads();

    uint32_t Tkey = 0, idx_cut = 0xFFFFFFFFu;

    if (!fb) {
        // ------------- histogram the 1024 thread-maxes (11-bit bins), aggregated atomics -------------
        uint32_t bin = mymax >> 21;
        unsigned mm = __match_any_sync(0xffffffffu, bin);
        if (lane == __ffs(mm) - 1) atomicAdd(&h[bin], (uint32_t)__popc(mm));
        __syncthreads();

        // k-th largest thread-max is >= selected bin's floor => count(keys >= Tfloor) >= k
        suffix_select(h, 2, HWORDS, k, s_wtot, s_sel);
        const uint32_t Tfloor = s_sel[0] << 21;

        // ------------- compaction from registers: count, ONE atomic, write -------------
        int c = 0;
        #pragma unroll
        for (int i = 0; i < EPT4; i++) {
            c += (kk[i].x >= Tfloor) + (kk[i].y >= Tfloor)
               + (kk[i].z >= Tfloor) + (kk[i].w >= Tfloor);
        }
        if (c > 0) {
            unsigned p = atomicAdd(&s_var[0], (uint32_t)c);
            #pragma unroll
            for (int i = 0; i < EPT4; i++) {
                int base = (i * THREADS + t) * 4;
                if (kk[i].x >= Tfloor && p < CAP) { ckey[p] = kk[i].x; cidx[p] = (uint16_t)(base);     p++; }
                if (kk[i].y >= Tfloor && p < CAP) { ckey[p] = kk[i].y; cidx[p] = (uint16_t)(base + 1); p++; }
                if (kk[i].z >= Tfloor && p < CAP) { ckey[p] = kk[i].z; cidx[p] = (uint16_t)(base + 2); p++; }
                if (kk[i].w >= Tfloor && p < CAP) { ckey[p] = kk[i].w; cidx[p] = (uint16_t)(base + 3); p++; }
            }
        }
        __syncthreads();
        const unsigned n = s_var[0];

        if (n > CAP) {
            fb = true;
        } else {
            // ------------- exact k-th by composite (key desc, idx asc): rank count -------------
            // ck48 = (key << 16) | (0xFFFF - idx); all distinct; n >= k guaranteed.
            for (unsigned i = t; i < n; i += THREADS) {
                unsigned long long cki =
                    ((unsigned long long)ckey[i] << 16) | (unsigned long long)(0xFFFFu - cidx[i]);
                int cnt = 0;
                for (unsigned j = 0; j < n; j++) {
                    unsigned long long ckj =
                        ((unsigned long long)ckey[j] << 16) | (unsigned long long)(0xFFFFu - cidx[j]);
                    cnt += (ckj > cki);
                }
                if (cnt == k - 1) {   // exactly one winner
                    s_var[1] = (uint32_t)(cki & 0xFFFFFFFFu);
                    s_var[2] = (uint32_t)(cki >> 32);
                }
            }
            __syncthreads();
            unsigned long long cut =
                ((unsigned long long)s_var[2] << 32) | (unsigned long long)s_var[1];
            Tkey    = (uint32_t)(cut >> 16);
            idx_cut = 0xFFFFu - (uint32_t)(cut & 0xFFFFu);
        }
    }

    // ---------------- FALLBACK: register-sourced 3-pass radix select ----------------
    if (fb) {
        __syncthreads();
        // pass 1: key bits [31:21]
        clear_hist(h);
        __syncthreads();
        #pragma unroll
        for (int i = 0; i < EPT4; i++) {
            atomicAdd(&h[kk[i].x >> 21], 1u);
            atomicAdd(&h[kk[i].y >> 21], 1u);
            atomicAdd(&h[kk[i].z >> 21], 1u);
            atomicAdd(&h[kk[i].w >> 21], 1u);
        }
        __syncthreads();
        suffix_select(h, 2, 2048, k, s_wtot, s_sel);
        const uint32_t b1 = s_sel[0];
        const int      k1 = (int)s_sel[1];

        // pass 2: key bits [20:10] among prefix matches
        clear_hist(h);
        __syncthreads();
        #pragma unroll
        for (int i = 0; i < EPT4; i++) {
            if ((kk[i].x >> 21) == b1) atomicAdd(&h[(kk[i].x >> 10) & 0x7FFu], 1u);
            if ((kk[i].y >> 21) == b1) atomicAdd(&h[(kk[i].y >> 10) & 0x7FFu], 1u);
            if ((kk[i].z >> 21) == b1) atomicAdd(&h[(kk[i].z >> 10) & 0x7FFu], 1u);
            if ((kk[i].w >> 21) == b1) atomicAdd(&h[(kk[i].w >> 10) & 0x7FFu], 1u);
        }
        __syncthreads();
        suffix_select(h, 2, 2048, k1, s_wtot, s_sel);
        const uint32_t prefix22 = (b1 << 11) | s_sel[0];
        const int      k2       = (int)s_sel[1];

        // pass 3: key bits [9:0]
        clear_hist(h);
        __syncthreads();
        #pragma unroll
        for (int i = 0; i < EPT4; i++) {
            if ((kk[i].x >> 10) == prefix22) atomicAdd(&h[kk[i].x & 0x3FFu], 1u);
            if ((kk[i].y >> 10) == prefix22) atomicAdd(&h[kk[i].y & 0x3FFu], 1u);
            if ((kk[i].z >> 10) == prefix22) atomicAdd(&h[kk[i].z & 0x3FFu], 1u);
            if ((kk[i].w >> 10) == prefix22) atomicAdd(&h[kk[i].w & 0x3FFu], 1u);
        }
        __syncthreads();
        suffix_select(h, 1, 1024, k2, s_wtot, s_sel);
        Tkey = (prefix22 << 10) | s_sel[0];
        const int m    = (int)s_sel[1];
        const int n_eq = (int)s_sel[2];

        idx_cut = 0xFFFFFFFFu;
        if (n_eq != m) {
            // counting binary search on index for the tie cut
            int lo = 0, hi = NCOLS - 1;
            while (lo < hi) {
                int mid = (lo + hi) >> 1;
                if (t == 0) s_var[3] = 0;
                __syncthreads();
                int local = 0;
                #pragma unroll
                for (int i = 0; i < EPT4; i++) {
                    int base = (i * THREADS + t) * 4;
                    local += (kk[i].x == Tkey && base     <= mid);
                    local += (kk[i].y == Tkey && base + 1 <= mid);
                    local += (kk[i].z == Tkey && base + 2 <= mid);
                    local += (kk[i].w == Tkey && base + 3 <= mid);
                }
                #pragma unroll
                for (int d = 16; d; d >>= 1) local += __shfl_down_sync(0xffffffffu, local, d);
                if (lane == 0 && local) atomicAdd(&s_var[3], (uint32_t)local);
                __syncthreads();
                if ((int)s_var[3] >= m) hi = mid; else lo = mid + 1;
                __syncthreads();
            }
            idx_cut = (uint32_t)lo;
        }
    }

    // ---------------- P5: output from registers. keep iff key > T, or key == T && idx <= idx_cut ----------------
    #pragma unroll
    for (int i = 0; i < EPT4; i++) {
        uint32_t base = (uint32_t)(i * THREADS + t) * 4u;
        float4 o;
        o.x = (kk[i].x > Tkey || (kk[i].x == Tkey && base      <= idx_cut)) ? key2f(kk[i].x) : 0.0f;
        o.y = (kk[i].y > Tkey || (kk[i].y == Tkey && base + 1u <= idx_cut)) ? key2f(kk[i].y) : 0.0f;
        o.z = (kk[i].z > Tkey || (kk[i].z == Tkey && base + 2u <= idx_cut)) ? key2f(kk[i].z) : 0.0f;
        o.w = (kk[i].w > Tkey || (kk[i].w == Tkey && base + 3u <= idx_cut)) ? key2f(kk[i].w) : 0.0f;
        __stcs(&xout[i * THREADS + t], o);
    }
}

extern "C" void kernel_launch(void* const* d_in, const int* in_sizes, int n_in,
                              void* d_out, int out_size)
{
    int xi = 0, ki = 1;
    if (n_in >= 2 && in_sizes[1] > in_sizes[0]) { xi = 1; ki = 0; }

    const float* x  = (const float*)d_in[xi];
    const int*   kp = (const int*)  d_in[ki];
    float*       out = (float*)d_out;

    int nrows = in_sizes[xi] / NCOLS;

    cudaFuncSetAttribute(topk_filter_kernel,
                         cudaFuncAttributeMaxDynamicSharedMemorySize, SMEM_BYTES);
    topk_filter_kernel<<<nrows, THREADS, SMEM_BYTES>>>(x, kp, out);
}